// round 1
// baseline (speedup 1.0000x reference)
#include <cuda_runtime.h>

#define Bq   16
#define Kq   32
#define Lq   1024
#define Dq   128
#define NEWL 48

// ---- scratch (no allocs allowed) ----
__device__ int   g_seg[Bq * Lq];
__device__ float g_counts[Bq * NEWL];
__device__ float g_tsum[Bq * NEWL];

#define NEG_INF __int_as_float(0xff800000)

// K1: segment index per (b,l)
__global__ void seg_kernel(const float* __restrict__ et) {
    int i = blockIdx.x * blockDim.x + threadIdx.x;
    if (i < Bq * Lq) {
        float t = et[i];
        int s = (t >= 0.f && t < (float)NEWL) ? (int)t : NEWL;
        g_seg[i] = s;
    }
}

// K2: deterministic counts + tsum per (b, s). grid=B, block=64 (48 active).
__global__ void stats_kernel(const float* __restrict__ et) {
    int b = blockIdx.x;
    int s = threadIdx.x;
    if (s >= NEWL) return;
    const float* row = et + b * Lq;
    float cnt = 0.f, ts = 0.f;
    for (int l = 0; l < Lq; ++l) {
        float t = row[l];
        int sg = (t >= 0.f && t < (float)NEWL) ? (int)t : NEWL;
        if (sg == s) { cnt += 1.f; ts += t; }
    }
    g_counts[b * NEWL + s] = cnt;
    g_tsum[b * NEWL + s]   = ts;
}

// K3: segment max over L for each (b,k,d). One block per (b,k), thread = d.
// Reads 512B coalesced per l; accumulates into shared smax[48][128].
// Writes new_h0 (B,K,48,D) — contiguous 24KB chunk per block.
__global__ void __launch_bounds__(Dq) segmax_kernel(const float* __restrict__ h0,
                                                    float* __restrict__ out_h) {
    const int bk = blockIdx.x;          // b*K + k
    const int b  = bk >> 5;             // K = 32
    const int t  = threadIdx.x;         // d index

    __shared__ float smax[NEWL * Dq];   // 24 KB
    __shared__ int   sseg[Lq];          // 4 KB

    #pragma unroll
    for (int i = t; i < NEWL * Dq; i += Dq) smax[i] = NEG_INF;
    const int* gs = g_seg + b * Lq;
    for (int i = t; i < Lq; i += Dq) sseg[i] = gs[i];
    __syncthreads();

    const float* base = h0 + (long long)bk * Lq * Dq + t;
    #pragma unroll 8
    for (int l = 0; l < Lq; ++l) {
        float v = base[(long long)l * Dq];
        int   s = sseg[l];
        if (s < NEWL) {
            float* p = &smax[s * Dq + t];
            float cur = *p;
            *p = fmaxf(cur, v);
        }
    }
    // no sync needed: each thread only reads the column it wrote

    float* o = out_h + (long long)bk * NEWL * Dq + t;
    const float* cptr = g_counts + b * NEWL;
    #pragma unroll 4
    for (int s = 0; s < NEWL; ++s) {
        float cnt = cptr[s];
        float v = smax[s * Dq + t];
        if (cnt < (float)Lq) v = fmaxf(v, 0.f);   // include_zero; empty seg -inf -> 0
        o[s * Dq] = v;
    }
}

// K4: msum per (b,k,s) (exact: mask is 0/1), plus pad_mask and event_time outputs.
__global__ void pad_kernel(const float* __restrict__ npm,
                           float* __restrict__ out_pm,
                           float* __restrict__ out_et) {
    const int bk = blockIdx.x;
    const int b  = bk >> 5;
    const int t  = threadIdx.x;

    __shared__ float acc[NEWL];
    if (t < NEWL) acc[t] = 0.f;
    __syncthreads();

    const float* row = npm + (long long)bk * Lq;
    const int*   gs  = g_seg + b * Lq;
    for (int l = t; l < Lq; l += blockDim.x) {
        int s = gs[l];
        float m = row[l];
        if (s < NEWL && m != 0.f) atomicAdd(&acc[s], m);  // sums of 0/1 -> exact
    }
    __syncthreads();

    if (t < NEWL) {
        float cnt   = g_counts[b * NEWL + t];
        float denom = fmaxf(cnt, 1.f);
        out_pm[bk * NEWL + t] = acc[t] / denom;
        out_et[bk * NEWL + t] = g_tsum[b * NEWL + t] / denom;
    }
}

// K5: almat (B,K,L,48) one-hot write, float4 stores (12 per row).
__global__ void almat_kernel(float* __restrict__ out_a) {
    long long g = (long long)blockIdx.x * blockDim.x + threadIdx.x; // float4 idx
    const long long total4 = (long long)Bq * Kq * Lq * NEWL / 4;    // 6,291,456
    if (g >= total4) return;
    long long row = g / 12;              // (b,k,l) flat
    int q = (int)(g - row * 12);         // which float4 in the 48-row
    int l = (int)(row & (Lq - 1));
    int b = (int)(row >> 15);            // row / (K*L), K*L = 2^15
    int s = g_seg[b * Lq + l];
    float4 v = make_float4(0.f, 0.f, 0.f, 0.f);
    int base = q * 4;
    int off = s - base;
    if (off >= 0 && off < 4) (&v.x)[off] = 1.f;
    reinterpret_cast<float4*>(out_a)[g] = v;
}

extern "C" void kernel_launch(void* const* d_in, const int* in_sizes, int n_in,
                              void* d_out, int out_size) {
    const float* h0  = (const float*)d_in[0];
    const float* et  = (const float*)d_in[1];
    const float* npm = (const float*)d_in[2];
    float* out = (float*)d_out;

    // packed output offsets (floats)
    float* o_h  = out;                         // new_h0:        (16,32,48,128) = 3,145,728
    float* o_et = out + 3145728;               // new_event_time:(16,32,48)     =    24,576
    float* o_pm = out + 3145728 + 24576;       // new_pad_mask:  (16,32,48)     =    24,576
    float* o_a  = out + 3145728 + 24576 + 24576; // almat:       (16,32,1024,48)= 25,165,824

    seg_kernel  <<<(Bq * Lq + 255) / 256, 256>>>(et);
    stats_kernel<<<Bq, 64>>>(et);
    segmax_kernel<<<Bq * Kq, Dq>>>(h0, o_h);
    pad_kernel  <<<Bq * Kq, 256>>>(npm, o_pm, o_et);
    almat_kernel<<<(int)((6291456 + 255) / 256), 256>>>(o_a);
}

// round 2
// speedup vs baseline: 6.1497x; 6.1497x over previous
#include <cuda_runtime.h>

#define Bq   16
#define Kq   32
#define Lq   1024
#define Dq   128
#define NEWL 48

// ---- scratch (no allocs allowed) ----
__device__ int   g_seg[Bq * Lq];
__device__ int   g_order[Bq * Lq];     // L indices sorted by segment, per batch
__device__ int   g_off[Bq * (NEWL + 1)];
__device__ float g_counts[Bq * NEWL];
__device__ float g_tsum[Bq * NEWL];

#define NEG_INF __int_as_float(0xff800000)

// K1: per-batch counting sort of l by segment + counts + tsum.
// grid = B, block = 1024 (thread = l).
__global__ void __launch_bounds__(Lq) prep_kernel(const float* __restrict__ et) {
    const int b = blockIdx.x;
    const int l = threadIdx.x;

    __shared__ int   cnt[NEWL + 1];
    __shared__ int   off[NEWL + 1];
    __shared__ int   cur[NEWL + 1];
    __shared__ float ts[NEWL];

    if (l <= NEWL) { cnt[l] = 0; cur[l] = 0; }
    if (l < NEWL)  ts[l] = 0.f;
    __syncthreads();

    float t = et[b * Lq + l];
    int   s = (t >= 0.f && t < (float)NEWL) ? (int)t : NEWL;
    g_seg[b * Lq + l] = s;
    atomicAdd(&cnt[s], 1);
    if (s < NEWL) atomicAdd(&ts[s], t);
    __syncthreads();

    if (l == 0) {
        int a = 0;
        #pragma unroll
        for (int i = 0; i <= NEWL; ++i) { off[i] = a; a += cnt[i]; }
    }
    __syncthreads();

    int pos = off[s] + atomicAdd(&cur[s], 1);
    g_order[b * Lq + pos] = l;

    if (l < NEWL) {
        g_counts[b * NEWL + l] = (float)cnt[l];
        g_tsum[b * NEWL + l]   = ts[l];
    }
    if (l <= NEWL) g_off[b * (NEWL + 1) + l] = off[l];
}

// K2: fused segmax + pad_mask + event_time.
// grid = (NEWL, B*K), block = 128 (thread = d). Register max, 4-way MLP.
__global__ void __launch_bounds__(Dq) segmax_kernel(const float* __restrict__ h0,
                                                    const float* __restrict__ npm,
                                                    float* __restrict__ o_h,
                                                    float* __restrict__ o_pm,
                                                    float* __restrict__ o_et) {
    const int s  = blockIdx.x;           // 0..47
    const int bk = blockIdx.y;           // 0..511
    const int b  = bk >> 5;              // K = 32
    const int t  = threadIdx.x;          // d

    const int off = g_off[b * (NEWL + 1) + s];
    const int cnt = g_off[b * (NEWL + 1) + s + 1] - off;

    __shared__ int lst[Lq];
    for (int i = t; i < cnt; i += Dq) lst[i] = g_order[b * Lq + off + i];
    __syncthreads();

    const float* base = h0 + (size_t)bk * Lq * Dq + t;
    float a0 = NEG_INF, a1 = NEG_INF, a2 = NEG_INF, a3 = NEG_INF;
    int i = 0;
    for (; i + 4 <= cnt; i += 4) {
        float v0 = base[(size_t)lst[i]     * Dq];
        float v1 = base[(size_t)lst[i + 1] * Dq];
        float v2 = base[(size_t)lst[i + 2] * Dq];
        float v3 = base[(size_t)lst[i + 3] * Dq];
        a0 = fmaxf(a0, v0); a1 = fmaxf(a1, v1);
        a2 = fmaxf(a2, v2); a3 = fmaxf(a3, v3);
    }
    for (; i < cnt; ++i) a0 = fmaxf(a0, base[(size_t)lst[i] * Dq]);
    float acc = fmaxf(fmaxf(a0, a1), fmaxf(a2, a3));

    if (cnt < Lq) acc = fmaxf(acc, 0.f);   // include_zero (empty segs: -inf -> 0)
    o_h[(size_t)bk * NEWL * Dq + s * Dq + t] = acc;

    // msum over this segment's list (exact: values are 0/1)
    float m = 0.f;
    const float* mrow = npm + (size_t)bk * Lq;
    for (int j = t; j < cnt; j += Dq) m += mrow[lst[j]];
    __shared__ float red[Dq];
    red[t] = m;
    __syncthreads();
    #pragma unroll
    for (int st = Dq / 2; st > 0; st >>= 1) {
        if (t < st) red[t] += red[t + st];
        __syncthreads();
    }
    if (t == 0) {
        float c     = g_counts[b * NEWL + s];
        float denom = fmaxf(c, 1.f);
        o_pm[bk * NEWL + s] = red[0] / denom;
        o_et[bk * NEWL + s] = g_tsum[b * NEWL + s] / denom;
    }
}

// K3: almat (B,K,L,48) one-hot write, float4 stores (12 per (b,k,l) row).
__global__ void almat_kernel(float* __restrict__ out_a) {
    long long g = (long long)blockIdx.x * blockDim.x + threadIdx.x;
    const long long total4 = (long long)Bq * Kq * Lq * NEWL / 4;   // 6,291,456
    if (g >= total4) return;
    long long row = g / 12;              // (b,k,l) flat
    int q = (int)(g - row * 12);
    int l = (int)(row & (Lq - 1));
    int b = (int)(row >> 15);            // / (K*L), K*L = 2^15
    int s = g_seg[b * Lq + l];
    float4 v = make_float4(0.f, 0.f, 0.f, 0.f);
    int o = s - q * 4;
    if (o >= 0 && o < 4) (&v.x)[o] = 1.f;
    reinterpret_cast<float4*>(out_a)[g] = v;
}

extern "C" void kernel_launch(void* const* d_in, const int* in_sizes, int n_in,
                              void* d_out, int out_size) {
    const float* h0  = (const float*)d_in[0];
    const float* et  = (const float*)d_in[1];
    const float* npm = (const float*)d_in[2];
    float* out = (float*)d_out;

    float* o_h  = out;                              // (16,32,48,128) = 3,145,728
    float* o_et = out + 3145728;                    // (16,32,48)     =    24,576
    float* o_pm = out + 3145728 + 24576;            // (16,32,48)     =    24,576
    float* o_a  = out + 3145728 + 24576 + 24576;    // (16,32,1024,48)= 25,165,824

    prep_kernel<<<Bq, Lq>>>(et);
    dim3 grid(NEWL, Bq * Kq);
    segmax_kernel<<<grid, Dq>>>(h0, npm, o_h, o_pm, o_et);
    almat_kernel<<<(int)((6291456 + 255) / 256), 256>>>(o_a);
}

// round 3
// speedup vs baseline: 6.6864x; 1.0873x over previous
#include <cuda_runtime.h>

#define Bq   16
#define Kq   32
#define Lq   1024
#define Dq   128
#define NEWL 48

// ---- scratch (no allocs allowed) ----
__device__ int   g_seg[Bq * Lq];
__device__ int   g_order[Bq * Lq];     // L indices sorted by segment, per batch
__device__ int   g_off[Bq * (NEWL + 1)];
__device__ float g_counts[Bq * NEWL];
__device__ float g_tsum[Bq * NEWL];

#define NEG_INF __int_as_float(0xff800000)

// K1: per-batch counting sort of l by segment + counts + tsum.
// grid = B, block = 1024 (thread = l).
__global__ void __launch_bounds__(Lq) prep_kernel(const float* __restrict__ et) {
    const int b = blockIdx.x;
    const int l = threadIdx.x;

    __shared__ int   cnt[NEWL + 1];
    __shared__ int   off[NEWL + 1];
    __shared__ int   cur[NEWL + 1];
    __shared__ float ts[NEWL];

    if (l <= NEWL) { cnt[l] = 0; cur[l] = 0; }
    if (l < NEWL)  ts[l] = 0.f;
    __syncthreads();

    float t = et[b * Lq + l];
    int   s = (t >= 0.f && t < (float)NEWL) ? (int)t : NEWL;
    g_seg[b * Lq + l] = s;
    atomicAdd(&cnt[s], 1);
    if (s < NEWL) atomicAdd(&ts[s], t);
    __syncthreads();

    // parallel exclusive prefix: thread s sums cnt[0..s) (smem broadcast reads)
    if (l <= NEWL) {
        int a = 0;
        for (int i = 0; i < l; ++i) a += cnt[i];
        off[l] = a;
    }
    __syncthreads();

    int pos = off[s] + atomicAdd(&cur[s], 1);
    g_order[b * Lq + pos] = l;

    if (l < NEWL) {
        g_counts[b * NEWL + l] = (float)cnt[l];
        g_tsum[b * NEWL + l]   = ts[l];
    }
    if (l <= NEWL) g_off[b * (NEWL + 1) + l] = off[l];
}

// K2: fused segmax + pad_mask + event_time.
// grid = (NEWL, B*K), block = 128 (4 warps).
// Warp w, lane j: float4 column j, rows i = w, w+4, ... -> LDG.128, MLP over rows.
__global__ void __launch_bounds__(Dq) segmax_kernel(const float* __restrict__ h0,
                                                    const float* __restrict__ npm,
                                                    float* __restrict__ o_h,
                                                    float* __restrict__ o_pm,
                                                    float* __restrict__ o_et) {
    const int s  = blockIdx.x;           // 0..47
    const int bk = blockIdx.y;           // 0..511
    const int b  = bk >> 5;              // K = 32
    const int t  = threadIdx.x;
    const int w  = t >> 5;               // warp 0..3
    const int j  = t & 31;               // lane = float4 col

    const int off = g_off[b * (NEWL + 1) + s];
    const int cnt = g_off[b * (NEWL + 1) + s + 1] - off;

    __shared__ int    lst[Lq];
    __shared__ float4 sacc[4 * 32];      // per-warp partial maxes
    __shared__ float  sred[4];           // msum partials

    for (int i = t; i < cnt; i += Dq) lst[i] = g_order[b * Lq + off + i];
    __syncthreads();

    const float4* base = reinterpret_cast<const float4*>(h0 + (size_t)bk * Lq * Dq) + j;
    float4 a = make_float4(NEG_INF, NEG_INF, NEG_INF, NEG_INF);
    for (int i = w; i < cnt; i += 4) {
        float4 v = base[(size_t)lst[i] * 32];
        a.x = fmaxf(a.x, v.x); a.y = fmaxf(a.y, v.y);
        a.z = fmaxf(a.z, v.z); a.w = fmaxf(a.w, v.w);
    }
    sacc[w * 32 + j] = a;

    // msum over this segment's list (exact: values are 0/1) — warp-shuffle reduce
    float m = 0.f;
    const float* mrow = npm + (size_t)bk * Lq;
    for (int i = t; i < cnt; i += Dq) m += mrow[lst[i]];
    #pragma unroll
    for (int d = 16; d > 0; d >>= 1) m += __shfl_down_sync(0xffffffffu, m, d);
    if (j == 0) sred[w] = m;
    __syncthreads();

    if (w == 0) {
        float4 v0 = sacc[j], v1 = sacc[32 + j], v2 = sacc[64 + j], v3 = sacc[96 + j];
        float4 r;
        r.x = fmaxf(fmaxf(v0.x, v1.x), fmaxf(v2.x, v3.x));
        r.y = fmaxf(fmaxf(v0.y, v1.y), fmaxf(v2.y, v3.y));
        r.z = fmaxf(fmaxf(v0.z, v1.z), fmaxf(v2.z, v3.z));
        r.w = fmaxf(fmaxf(v0.w, v1.w), fmaxf(v2.w, v3.w));
        if (cnt < Lq) {                   // include_zero (empty segs: -inf -> 0)
            r.x = fmaxf(r.x, 0.f); r.y = fmaxf(r.y, 0.f);
            r.z = fmaxf(r.z, 0.f); r.w = fmaxf(r.w, 0.f);
        }
        reinterpret_cast<float4*>(o_h)[(size_t)bk * NEWL * 32 + s * 32 + j] = r;

        if (j == 0) {
            float msum  = sred[0] + sred[1] + sred[2] + sred[3];
            float c     = g_counts[b * NEWL + s];
            float denom = fmaxf(c, 1.f);
            o_pm[bk * NEWL + s] = msum / denom;
            o_et[bk * NEWL + s] = g_tsum[b * NEWL + s] / denom;
        }
    }
}

// K3: almat (B,K,L,48) one-hot write, float4 stores (12 per (b,k,l) row).
__global__ void almat_kernel(float* __restrict__ out_a) {
    long long g = (long long)blockIdx.x * blockDim.x + threadIdx.x;
    const long long total4 = (long long)Bq * Kq * Lq * NEWL / 4;   // 6,291,456
    if (g >= total4) return;
    long long row = g / 12;              // (b,k,l) flat
    int q = (int)(g - row * 12);
    int l = (int)(row & (Lq - 1));
    int b = (int)(row >> 15);            // / (K*L), K*L = 2^15
    int s = g_seg[b * Lq + l];
    float4 v = make_float4(0.f, 0.f, 0.f, 0.f);
    int o = s - q * 4;
    if (o >= 0 && o < 4) (&v.x)[o] = 1.f;
    reinterpret_cast<float4*>(out_a)[g] = v;
}

extern "C" void kernel_launch(void* const* d_in, const int* in_sizes, int n_in,
                              void* d_out, int out_size) {
    const float* h0  = (const float*)d_in[0];
    const float* et  = (const float*)d_in[1];
    const float* npm = (const float*)d_in[2];
    float* out = (float*)d_out;

    float* o_h  = out;                              // (16,32,48,128) = 3,145,728
    float* o_et = out + 3145728;                    // (16,32,48)     =    24,576
    float* o_pm = out + 3145728 + 24576;            // (16,32,48)     =    24,576
    float* o_a  = out + 3145728 + 24576 + 24576;    // (16,32,1024,48)= 25,165,824

    prep_kernel<<<Bq, Lq>>>(et);
    dim3 grid(NEWL, Bq * Kq);
    segmax_kernel<<<grid, Dq>>>(h0, npm, o_h, o_pm, o_et);
    almat_kernel<<<(int)((6291456 + 255) / 256), 256>>>(o_a);
}